// round 12
// baseline (speedup 1.0000x reference)
#include <cuda_runtime.h>
#include <math_constants.h>
#include <cstdint>

#define NOUT   257
#define NBATCH 32768
#define RPB    8

__device__ __forceinline__ void cmul(float ar, float ai, float br, float bi,
                                     float& cr, float& ci)
{
    cr = ar * br - ai * bi;
    ci = ar * bi + ai * br;
}

// ---- f32x2 packed helpers (sm_103a native) ----
__device__ __forceinline__ uint64_t pk2(float lo, float hi) {
    uint64_t r;
    asm("mov.b64 %0, {%1, %2};" : "=l"(r) : "f"(lo), "f"(hi));
    return r;
}
__device__ __forceinline__ void upk2(uint64_t v, float& lo, float& hi) {
    asm("mov.b64 {%0, %1}, %2;" : "=f"(lo), "=f"(hi) : "l"(v));
}
__device__ __forceinline__ uint64_t fma2(uint64_t a, uint64_t b, uint64_t c) {
    uint64_t d;
    asm("fma.rn.f32x2 %0, %1, %2, %3;" : "=l"(d) : "l"(a), "l"(b), "l"(c));
    return d;
}
__device__ __forceinline__ uint64_t mul2(uint64_t a, uint64_t b) {
    uint64_t d;
    asm("mul.rn.f32x2 %0, %1, %2;" : "=l"(d) : "l"(a), "l"(b));
    return d;
}

#define ONE2  0x3F8000003F800000ull   // ( 1.0f,  1.0f)
#define NEG2  0xBF800000BF800000ull   // (-1.0f, -1.0f)

// Packed cross-lane DIF stage, butterfly distance H (select-free).
template<int H>
__device__ __forceinline__ void dif_stage_p(uint64_t* Zr, uint64_t* Zi,
                                            uint64_t s2, uint64_t wc2,
                                            uint64_t nws2, uint64_t ws2)
{
    #pragma unroll
    for (int q = 0; q < 4; ++q) {
        const uint64_t orr = __shfl_xor_sync(0xffffffffu, Zr[q], H);
        const uint64_t oii = __shfl_xor_sync(0xffffffffu, Zi[q], H);
        const uint64_t dr = fma2(s2, Zr[q], orr);
        const uint64_t di = fma2(s2, Zi[q], oii);
        Zr[q] = fma2(wc2, dr, mul2(nws2, di));
        Zi[q] = fma2(wc2, di, mul2(ws2,  dr));
    }
}

__global__ __launch_bounds__(256)
void rfft512_warp(const float* __restrict__ x,
                  float* __restrict__ yre,
                  float* __restrict__ yim)
{
    // Z staged interleaved (re,im) at float2 addr a = k + (k>>4)
    // (conflict-free scatter AND gather).
    __shared__ float2 ssz[RPB][272];

    const int lane = threadIdx.x & 31;
    const int w    = threadIdx.x >> 5;
    const long long row = (long long)blockIdx.x * RPB + w;
    const float* xr = x + row * 512;
    float2* sz = ssz[w];

    // ---- single sincosf: bc,bs = W_512^lane; all twiddles derive from it ----
    float bc, bs;
    __sincosf(-2.0f * CUDART_PI_F * (float)lane / 512.0f, &bs, &bc);

    // ---- load z[m] = 0.5*(x[2m] + i x[2m+1]), m = lane + 32 r ----
    float zr[8], zi[8];
    #pragma unroll
    for (int r = 0; r < 8; ++r) {
        float2 v = *reinterpret_cast<const float2*>(xr + 2 * (lane + 32 * r));
        zr[r] = 0.5f * v.x; zi[r] = 0.5f * v.y;
    }

    // ---- step A: radix-8 DIF over reg index -> slot r holds k2 = br3(r) ----
    const float C = 0.70710678118654752440f;
    {   // h=4, twiddles W8^{0..3}
        float dr, di;
        dr = zr[0] - zr[4]; di = zi[0] - zi[4];
        zr[0] += zr[4]; zi[0] += zi[4];
        zr[4] = dr; zi[4] = di;

        dr = zr[1] - zr[5]; di = zi[1] - zi[5];
        zr[1] += zr[5]; zi[1] += zi[5];
        zr[5] = C * (dr + di); zi[5] = C * (di - dr);

        dr = zr[2] - zr[6]; di = zi[2] - zi[6];
        zr[2] += zr[6]; zi[2] += zi[6];
        zr[6] = di; zi[6] = -dr;

        dr = zr[3] - zr[7]; di = zi[3] - zi[7];
        zr[3] += zr[7]; zi[3] += zi[7];
        zr[7] = C * (di - dr); zi[7] = -C * (dr + di);
    }
    {   // h=2, twiddles 1, -i
        float dr, di;
        dr = zr[0] - zr[2]; di = zi[0] - zi[2];
        zr[0] += zr[2]; zi[0] += zi[2]; zr[2] = dr; zi[2] = di;

        dr = zr[1] - zr[3]; di = zi[1] - zi[3];
        zr[1] += zr[3]; zi[1] += zi[3]; zr[3] = di; zi[3] = -dr;

        dr = zr[4] - zr[6]; di = zi[4] - zi[6];
        zr[4] += zr[6]; zi[4] += zi[6]; zr[6] = dr; zi[6] = di;

        dr = zr[5] - zr[7]; di = zi[5] - zi[7];
        zr[5] += zr[7]; zi[5] += zi[7]; zr[7] = di; zi[7] = -dr;
    }
    {   // h=1
        float dr, di;
        dr = zr[0] - zr[1]; di = zi[0] - zi[1];
        zr[0] += zr[1]; zi[0] += zi[1]; zr[1] = dr; zi[1] = di;
        dr = zr[2] - zr[3]; di = zi[2] - zi[3];
        zr[2] += zr[3]; zi[2] += zi[3]; zr[3] = dr; zi[3] = di;
        dr = zr[4] - zr[5]; di = zi[4] - zi[5];
        zr[4] += zr[5]; zi[4] += zi[5]; zr[5] = dr; zi[5] = di;
        dr = zr[6] - zr[7]; di = zi[6] - zi[7];
        zr[6] += zr[7]; zi[6] += zi[7]; zr[7] = dr; zi[7] = di;
    }

    // ---- step B: multiply slot (k2) by W_256^{lane*k2}; w1 = (bc+ibs)^2 ----
    float w4r, w4i;   // kept for u-derivation below
    {
        const float w1r = bc * bc - bs * bs;
        const float w1i = 2.0f * bc * bs;
        float w2r, w2i, w3r, w3i, w5r, w5i, w6r, w6i, w7r, w7i;
        cmul(w1r, w1i, w1r, w1i, w2r, w2i);
        cmul(w2r, w2i, w1r, w1i, w3r, w3i);
        cmul(w2r, w2i, w2r, w2i, w4r, w4i);
        cmul(w4r, w4i, w1r, w1i, w5r, w5i);
        cmul(w3r, w3i, w3r, w3i, w6r, w6i);
        cmul(w4r, w4i, w3r, w3i, w7r, w7i);

        float tr, ti;
        cmul(zr[1], zi[1], w4r, w4i, tr, ti); zr[1] = tr; zi[1] = ti;  // k2=4
        cmul(zr[2], zi[2], w2r, w2i, tr, ti); zr[2] = tr; zi[2] = ti;  // k2=2
        cmul(zr[3], zi[3], w6r, w6i, tr, ti); zr[3] = tr; zi[3] = ti;  // k2=6
        cmul(zr[4], zi[4], w1r, w1i, tr, ti); zr[4] = tr; zi[4] = ti;  // k2=1
        cmul(zr[5], zi[5], w5r, w5i, tr, ti); zr[5] = tr; zi[5] = ti;  // k2=5
        cmul(zr[6], zi[6], w3r, w3i, tr, ti); zr[6] = tr; zi[6] = ti;  // k2=3
        cmul(zr[7], zi[7], w7r, w7i, tr, ti); zr[7] = tr; zi[7] = ti;  // k2=7
    }

    // ---- step C: 32-pt DIF across lanes, f32x2-packed over reg pairs ----
    {
        // u = W_32^{lane&15} = (lane&16 ? -1 : 1) * w1^8; w1^8 = w4^2.
        float uc = w4r * w4r - w4i * w4i;
        float us = 2.0f * w4r * w4i;
        if (lane & 16) { uc = -uc; us = -us; }
        const float p2c = uc * uc - us * us,     p2s = 2.0f * uc * us;
        const float p4c = p2c * p2c - p2s * p2s, p4s = 2.0f * p2c * p2s;
        const float p8c = p4c * p4c - p4s * p4s, p8s = 2.0f * p4c * p4s;

        uint64_t Zr[4], Zi[4];
        #pragma unroll
        for (int q = 0; q < 4; ++q) {
            Zr[q] = pk2(zr[2 * q], zr[2 * q + 1]);
            Zi[q] = pk2(zi[2 * q], zi[2 * q + 1]);
        }

        {   // H=16: w = u
            const bool hi = (lane & 16) != 0;
            const float wc = hi ?  uc : 1.0f;
            const float ws = hi ?  us : 0.0f;
            dif_stage_p<16>(Zr, Zi, hi ? NEG2 : ONE2,
                            pk2(wc, wc), pk2(-ws, -ws), pk2(ws, ws));
        }
        {   // H=8: w = -u^2
            const bool hi = (lane & 8) != 0;
            const float wc = hi ? -p2c : 1.0f;
            const float ws = hi ? -p2s : 0.0f;
            dif_stage_p<8>(Zr, Zi, hi ? NEG2 : ONE2,
                           pk2(wc, wc), pk2(-ws, -ws), pk2(ws, ws));
        }
        {   // H=4: w = -u^4
            const bool hi = (lane & 4) != 0;
            const float wc = hi ? -p4c : 1.0f;
            const float ws = hi ? -p4s : 0.0f;
            dif_stage_p<4>(Zr, Zi, hi ? NEG2 : ONE2,
                           pk2(wc, wc), pk2(-ws, -ws), pk2(ws, ws));
        }
        {   // H=2: w = -u^8
            const bool hi = (lane & 2) != 0;
            const float wc = hi ? -p8c : 1.0f;
            const float ws = hi ? -p8s : 0.0f;
            dif_stage_p<2>(Zr, Zi, hi ? NEG2 : ONE2,
                           pk2(wc, wc), pk2(-ws, -ws), pk2(ws, ws));
        }
        {   // H=1: w = 1 (twiddle-free)
            const uint64_t s2 = (lane & 1) ? NEG2 : ONE2;
            #pragma unroll
            for (int q = 0; q < 4; ++q) {
                const uint64_t orr = __shfl_xor_sync(0xffffffffu, Zr[q], 1);
                const uint64_t oii = __shfl_xor_sync(0xffffffffu, Zi[q], 1);
                Zr[q] = fma2(s2, Zr[q], orr);
                Zi[q] = fma2(s2, Zi[q], oii);
            }
        }

        #pragma unroll
        for (int q = 0; q < 4; ++q) {
            upk2(Zr[q], zr[2 * q], zr[2 * q + 1]);
            upk2(Zi[q], zi[2 * q], zi[2 * q + 1]);
        }
    }
    // lane l, slot r holds 0.5 * Z[k2 + 8*kappa], k2 = br3(r), kappa = br5(l)

    // ---- stage Z to smem (interleaved) at a = k + (k>>4): conflict-free ----
    {
        const int kap = __brev((unsigned)lane) >> 27;   // bitrev5(lane)
        const int base = 8 * kap + (kap >> 1);          // = 8kap + ((8kap+k2)>>4)
        const int K2M[8] = {0, 4, 2, 6, 1, 5, 3, 7};
        #pragma unroll
        for (int r = 0; r < 8; ++r)
            sz[base + K2M[r]] = make_float2(zr[r], zi[r]);
    }
    __syncwarp();

    // ---- pair untangle: k = 32j + lane (j=0..3) gives X[k] AND X[256-k] ----
    float* orow = yre + row * NOUT;
    float* irow = yim + row * NOUT;
    {
        // W_16^j, j = 0..3
        const float CJ[4] = { 1.0f,  0.92387953251128674f,
                              0.70710678118654757f,  0.38268343236508984f};
        const float SJ[4] = { 0.0f, -0.38268343236508977f,
                             -0.70710678118654746f, -0.92387953251128674f};

        #pragma unroll
        for (int j = 0; j < 4; ++j) {
            const int k  = 32 * j + lane;
            const int km = (256 - k) & 255;           // Z partner (wraps k=0 -> 0)

            const float2 Zk = sz[k + (k >> 4)];
            const float2 Zm = sz[km + (km >> 4)];

            const float Fer = Zk.x + Zm.x;
            const float Fei = Zk.y - Zm.y;
            const float For = Zk.y + Zm.y;
            const float Foi = Zm.x - Zk.x;

            // w = W_512^k = (bc + i bs) * W_16^j
            const float wc = fmaf(bc, CJ[j], -bs * SJ[j]);
            const float ws = fmaf(bc, SJ[j],  bs * CJ[j]);

            const float P = fmaf(wc, For, -ws * Foi);
            const float Q = fmaf(wc, Foi,  ws * For);

            orow[k] = Fer + P;          // X[k]
            irow[k] = Fei + Q;
            orow[256 - k] = Fer - P;    // X[256-k] (k=0 -> bin 256)
            irow[256 - k] = Q - Fei;
        }
        if (lane == 0) {                // self-paired bin 128: X = Zr - i*Zi
            const float2 Zc = sz[128 + (128 >> 4)];
            orow[128] =  2.0f * Zc.x;
            irow[128] = -2.0f * Zc.y;
        }
    }
}

extern "C" void kernel_launch(void* const* d_in, const int* in_sizes, int n_in,
                              void* d_out, int out_size)
{
    const float* x = (const float*)d_in[0];
    float* out = (float*)d_out;
    float* yre = out;                                  // [32768, 257]
    float* yim = out + (long long)NBATCH * NOUT;       // [32768, 257]

    rfft512_warp<<<NBATCH / RPB, 32 * RPB>>>(x, yre, yim);
}

// round 13
// speedup vs baseline: 1.0837x; 1.0837x over previous
#include <cuda_runtime.h>
#include <math_constants.h>
#include <cstdint>

#define NOUT   257
#define NBATCH 32768
#define RPB    8

__device__ __forceinline__ void cmul(float ar, float ai, float br, float bi,
                                     float& cr, float& ci)
{
    cr = ar * br - ai * bi;
    ci = ar * bi + ai * br;
}

// ---- f32x2 packed helpers (sm_103a native) ----
__device__ __forceinline__ uint64_t pk2(float lo, float hi) {
    uint64_t r;
    asm("mov.b64 %0, {%1, %2};" : "=l"(r) : "f"(lo), "f"(hi));
    return r;
}
__device__ __forceinline__ void upk2(uint64_t v, float& lo, float& hi) {
    asm("mov.b64 {%0, %1}, %2;" : "=f"(lo), "=f"(hi) : "l"(v));
}
__device__ __forceinline__ uint64_t fma2(uint64_t a, uint64_t b, uint64_t c) {
    uint64_t d;
    asm("fma.rn.f32x2 %0, %1, %2, %3;" : "=l"(d) : "l"(a), "l"(b), "l"(c));
    return d;
}
__device__ __forceinline__ uint64_t mul2(uint64_t a, uint64_t b) {
    uint64_t d;
    asm("mul.rn.f32x2 %0, %1, %2;" : "=l"(d) : "l"(a), "l"(b));
    return d;
}

#define ONE2  0x3F8000003F800000ull   // ( 1.0f,  1.0f)
#define NEG2  0xBF800000BF800000ull   // (-1.0f, -1.0f)

// Packed cross-lane DIF stage, butterfly distance H (select-free).
template<int H>
__device__ __forceinline__ void dif_stage_p(uint64_t* Zr, uint64_t* Zi,
                                            uint64_t s2, uint64_t wc2,
                                            uint64_t nws2, uint64_t ws2)
{
    #pragma unroll
    for (int q = 0; q < 4; ++q) {
        const uint64_t orr = __shfl_xor_sync(0xffffffffu, Zr[q], H);
        const uint64_t oii = __shfl_xor_sync(0xffffffffu, Zi[q], H);
        const uint64_t dr = fma2(s2, Zr[q], orr);
        const uint64_t di = fma2(s2, Zi[q], oii);
        Zr[q] = fma2(wc2, dr, mul2(nws2, di));
        Zi[q] = fma2(wc2, di, mul2(ws2,  dr));
    }
}

__global__ __launch_bounds__(256)
void rfft512_warp(const float* __restrict__ x,
                  float* __restrict__ yre,
                  float* __restrict__ yim)
{
    // Z staged interleaved (re,im) at float2 addr a = k + (k>>4)
    // (conflict-free scatter AND gather).
    __shared__ float2 ssz[RPB][272];

    const int lane = threadIdx.x & 31;
    const int w    = threadIdx.x >> 5;
    const long long row = (long long)blockIdx.x * RPB + w;
    const float* xr = x + row * 512;
    float2* sz = ssz[w];

    // ---- load z[m] = 0.5*(x[2m] + i x[2m+1]), m = lane + 32 r ----
    float zr[8], zi[8];
    #pragma unroll
    for (int r = 0; r < 8; ++r) {
        float2 v = *reinterpret_cast<const float2*>(xr + 2 * (lane + 32 * r));
        zr[r] = 0.5f * v.x; zi[r] = 0.5f * v.y;
    }

    // ---- step A: radix-8 DIF over reg index -> slot r holds k2 = br3(r) ----
    const float C = 0.70710678118654752440f;
    {   // h=4, twiddles W8^{0..3}
        float dr, di;
        dr = zr[0] - zr[4]; di = zi[0] - zi[4];
        zr[0] += zr[4]; zi[0] += zi[4];
        zr[4] = dr; zi[4] = di;

        dr = zr[1] - zr[5]; di = zi[1] - zi[5];
        zr[1] += zr[5]; zi[1] += zi[5];
        zr[5] = C * (dr + di); zi[5] = C * (di - dr);

        dr = zr[2] - zr[6]; di = zi[2] - zi[6];
        zr[2] += zr[6]; zi[2] += zi[6];
        zr[6] = di; zi[6] = -dr;

        dr = zr[3] - zr[7]; di = zi[3] - zi[7];
        zr[3] += zr[7]; zi[3] += zi[7];
        zr[7] = C * (di - dr); zi[7] = -C * (dr + di);
    }
    {   // h=2, twiddles 1, -i
        float dr, di;
        dr = zr[0] - zr[2]; di = zi[0] - zi[2];
        zr[0] += zr[2]; zi[0] += zi[2]; zr[2] = dr; zi[2] = di;

        dr = zr[1] - zr[3]; di = zi[1] - zi[3];
        zr[1] += zr[3]; zi[1] += zi[3]; zr[3] = di; zi[3] = -dr;

        dr = zr[4] - zr[6]; di = zi[4] - zi[6];
        zr[4] += zr[6]; zi[4] += zi[6]; zr[6] = dr; zi[6] = di;

        dr = zr[5] - zr[7]; di = zi[5] - zi[7];
        zr[5] += zr[7]; zi[5] += zi[7]; zr[7] = di; zi[7] = -dr;
    }
    {   // h=1
        float dr, di;
        dr = zr[0] - zr[1]; di = zi[0] - zi[1];
        zr[0] += zr[1]; zi[0] += zi[1]; zr[1] = dr; zi[1] = di;
        dr = zr[2] - zr[3]; di = zi[2] - zi[3];
        zr[2] += zr[3]; zi[2] += zi[3]; zr[3] = dr; zi[3] = di;
        dr = zr[4] - zr[5]; di = zi[4] - zi[5];
        zr[4] += zr[5]; zi[4] += zi[5]; zr[5] = dr; zi[5] = di;
        dr = zr[6] - zr[7]; di = zi[6] - zi[7];
        zr[6] += zr[7]; zi[6] += zi[7]; zr[7] = dr; zi[7] = di;
    }

    // ---- step B: multiply slot (k2) by W_256^{lane * k2} ----
    {
        float w1r, w1i;
        __sincosf(-2.0f * CUDART_PI_F * (float)lane / 256.0f, &w1i, &w1r);
        float w2r, w2i, w3r, w3i, w4r, w4i, w5r, w5i, w6r, w6i, w7r, w7i;
        cmul(w1r, w1i, w1r, w1i, w2r, w2i);
        cmul(w2r, w2i, w1r, w1i, w3r, w3i);
        cmul(w2r, w2i, w2r, w2i, w4r, w4i);
        cmul(w4r, w4i, w1r, w1i, w5r, w5i);
        cmul(w3r, w3i, w3r, w3i, w6r, w6i);
        cmul(w4r, w4i, w3r, w3i, w7r, w7i);

        float tr, ti;
        cmul(zr[1], zi[1], w4r, w4i, tr, ti); zr[1] = tr; zi[1] = ti;  // k2=4
        cmul(zr[2], zi[2], w2r, w2i, tr, ti); zr[2] = tr; zi[2] = ti;  // k2=2
        cmul(zr[3], zi[3], w6r, w6i, tr, ti); zr[3] = tr; zi[3] = ti;  // k2=6
        cmul(zr[4], zi[4], w1r, w1i, tr, ti); zr[4] = tr; zi[4] = ti;  // k2=1
        cmul(zr[5], zi[5], w5r, w5i, tr, ti); zr[5] = tr; zi[5] = ti;  // k2=5
        cmul(zr[6], zi[6], w3r, w3i, tr, ti); zr[6] = tr; zi[6] = ti;  // k2=3
        cmul(zr[7], zi[7], w7r, w7i, tr, ti); zr[7] = tr; zi[7] = ti;  // k2=7
    }

    // ---- step C: 32-pt DIF across lanes, f32x2-packed over reg pairs ----
    {
        float uc, us;   // u = W_32^{lane&15}
        __sincosf(-CUDART_PI_F * (float)(lane & 15) / 16.0f, &us, &uc);
        const float p2c = uc * uc - us * us,     p2s = 2.0f * uc * us;
        const float p4c = p2c * p2c - p2s * p2s, p4s = 2.0f * p2c * p2s;
        const float p8c = p4c * p4c - p4s * p4s, p8s = 2.0f * p4c * p4s;

        uint64_t Zr[4], Zi[4];
        #pragma unroll
        for (int q = 0; q < 4; ++q) {
            Zr[q] = pk2(zr[2 * q], zr[2 * q + 1]);
            Zi[q] = pk2(zi[2 * q], zi[2 * q + 1]);
        }

        {   // H=16: w = u
            const bool hi = (lane & 16) != 0;
            const float wc = hi ?  uc : 1.0f;
            const float ws = hi ?  us : 0.0f;
            dif_stage_p<16>(Zr, Zi, hi ? NEG2 : ONE2,
                            pk2(wc, wc), pk2(-ws, -ws), pk2(ws, ws));
        }
        {   // H=8: w = -u^2
            const bool hi = (lane & 8) != 0;
            const float wc = hi ? -p2c : 1.0f;
            const float ws = hi ? -p2s : 0.0f;
            dif_stage_p<8>(Zr, Zi, hi ? NEG2 : ONE2,
                           pk2(wc, wc), pk2(-ws, -ws), pk2(ws, ws));
        }
        {   // H=4: w = -u^4
            const bool hi = (lane & 4) != 0;
            const float wc = hi ? -p4c : 1.0f;
            const float ws = hi ? -p4s : 0.0f;
            dif_stage_p<4>(Zr, Zi, hi ? NEG2 : ONE2,
                           pk2(wc, wc), pk2(-ws, -ws), pk2(ws, ws));
        }
        {   // H=2: w = -u^8
            const bool hi = (lane & 2) != 0;
            const float wc = hi ? -p8c : 1.0f;
            const float ws = hi ? -p8s : 0.0f;
            dif_stage_p<2>(Zr, Zi, hi ? NEG2 : ONE2,
                           pk2(wc, wc), pk2(-ws, -ws), pk2(ws, ws));
        }
        {   // H=1: w = 1 (twiddle-free)
            const uint64_t s2 = (lane & 1) ? NEG2 : ONE2;
            #pragma unroll
            for (int q = 0; q < 4; ++q) {
                const uint64_t orr = __shfl_xor_sync(0xffffffffu, Zr[q], 1);
                const uint64_t oii = __shfl_xor_sync(0xffffffffu, Zi[q], 1);
                Zr[q] = fma2(s2, Zr[q], orr);
                Zi[q] = fma2(s2, Zi[q], oii);
            }
        }

        #pragma unroll
        for (int q = 0; q < 4; ++q) {
            upk2(Zr[q], zr[2 * q], zr[2 * q + 1]);
            upk2(Zi[q], zi[2 * q], zi[2 * q + 1]);
        }
    }
    // lane l, slot r holds 0.5 * Z[k2 + 8*kappa], k2 = br3(r), kappa = br5(l)

    // ---- stage Z to smem (interleaved) at a = k + (k>>4): conflict-free ----
    {
        const int kap = __brev((unsigned)lane) >> 27;   // bitrev5(lane)
        const int base = 8 * kap + (kap >> 1);          // = 8kap + ((8kap+k2)>>4)
        const int K2M[8] = {0, 4, 2, 6, 1, 5, 3, 7};
        #pragma unroll
        for (int r = 0; r < 8; ++r)
            sz[base + K2M[r]] = make_float2(zr[r], zi[r]);
    }
    __syncwarp();

    // ---- pair untangle: k = 32j + lane (j=0..3) gives X[k] AND X[256-k] ----
    float* orow = yre + row * NOUT;
    float* irow = yim + row * NOUT;
    {
        float bc, bs;   // W_512^lane
        __sincosf(-2.0f * CUDART_PI_F * (float)lane / 512.0f, &bs, &bc);

        // W_16^j, j = 0..3
        const float CJ[4] = { 1.0f,  0.92387953251128674f,
                              0.70710678118654757f,  0.38268343236508984f};
        const float SJ[4] = { 0.0f, -0.38268343236508977f,
                             -0.70710678118654746f, -0.92387953251128674f};

        #pragma unroll
        for (int j = 0; j < 4; ++j) {
            const int k  = 32 * j + lane;
            const int km = (256 - k) & 255;           // Z partner (wraps k=0 -> 0)

            const float2 Zk = sz[k + (k >> 4)];
            const float2 Zm = sz[km + (km >> 4)];

            const float Fer = Zk.x + Zm.x;
            const float Fei = Zk.y - Zm.y;
            const float For = Zk.y + Zm.y;
            const float Foi = Zm.x - Zk.x;

            // w = W_512^k = (bc + i bs) * W_16^j
            const float wc = fmaf(bc, CJ[j], -bs * SJ[j]);
            const float ws = fmaf(bc, SJ[j],  bs * CJ[j]);

            const float P = fmaf(wc, For, -ws * Foi);
            const float Q = fmaf(wc, Foi,  ws * For);

            orow[k] = Fer + P;          // X[k]
            irow[k] = Fei + Q;
            orow[256 - k] = Fer - P;    // X[256-k] (k=0 -> bin 256)
            irow[256 - k] = Q - Fei;
        }
        if (lane == 0) {                // self-paired bin 128: X = Zr - i*Zi
            const float2 Zc = sz[128 + (128 >> 4)];
            orow[128] =  2.0f * Zc.x;
            irow[128] = -2.0f * Zc.y;
        }
    }
}

extern "C" void kernel_launch(void* const* d_in, const int* in_sizes, int n_in,
                              void* d_out, int out_size)
{
    const float* x = (const float*)d_in[0];
    float* out = (float*)d_out;
    float* yre = out;                                  // [32768, 257]
    float* yim = out + (long long)NBATCH * NOUT;       // [32768, 257]

    rfft512_warp<<<NBATCH / RPB, 32 * RPB>>>(x, yre, yim);
}